// round 4
// baseline (speedup 1.0000x reference)
#include <cuda_runtime.h>
#include <cstdint>

#define dE 8
#define dH 1024
#define dI 4096
#define dN 2048
#define dK 2
#define dNK 4096

#define TM 128
#define TN 128
#define TBK 16
#define NTH 256

// smem word layouts (uint32 words)
#define A_ST 20
#define B_ST 132
#define A_SZ (128 * A_ST)            // per stage
#define B_SZ (TBK * B_ST)            // per stage
#define SA(s, r, c)   ((s) * A_SZ + (r) * A_ST + (c))
#define SB1_(s, k, n) (2 * A_SZ + (s) * B_SZ + (k) * B_ST + (n))
#define SB3_(s, k, n) (2 * A_SZ + 2 * B_SZ + (s) * B_SZ + (k) * B_ST + (n))
#define SMEM1_WORDS (2 * A_SZ + 4 * B_SZ)
#define SMEM2_WORDS (2 * A_SZ + 2 * B_SZ)

// ---- scratch (device globals; no runtime allocation) ----
__device__ int   g_pairs[dNK];
__device__ int   g_off[dE + 1];
__device__ float g_h[(size_t)dNK * dI];   // SwiGLU hidden (64 MB)
__device__ float g_y[(size_t)dNK * dH];   // per-pair weighted output (16 MB)

__device__ __forceinline__ uint32_t f2t(float f) {
    uint32_t u; asm("cvt.rna.tf32.f32 %0, %1;" : "=r"(u) : "f"(f)); return u;
}
__device__ __forceinline__ uint4 cvt4(float4 v) {
    uint4 o; o.x = f2t(v.x); o.y = f2t(v.y); o.z = f2t(v.z); o.w = f2t(v.w); return o;
}
__device__ __forceinline__ void mma_tf32(float* d, const uint32_t* a, const uint32_t* b) {
    asm volatile("mma.sync.aligned.m16n8k8.row.col.f32.tf32.tf32.f32 "
                 "{%0,%1,%2,%3}, {%4,%5,%6,%7}, {%8,%9}, {%0,%1,%2,%3};\n"
                 : "+f"(d[0]), "+f"(d[1]), "+f"(d[2]), "+f"(d[3])
                 : "r"(a[0]), "r"(a[1]), "r"(a[2]), "r"(a[3]),
                   "r"(b[0]), "r"(b[1]));
}

// ---- routing: histogram + scan + scatter, single CTA ----
__global__ void route_kernel(const int* __restrict__ idx) {
    __shared__ int s_cnt[dE], s_base[dE];
    int t = threadIdx.x;
    if (t < dE) s_cnt[t] = 0;
    __syncthreads();
    for (int p = t; p < dNK; p += blockDim.x) atomicAdd(&s_cnt[idx[p]], 1);
    __syncthreads();
    if (t == 0) {
        int acc = 0;
        for (int e = 0; e < dE; ++e) { g_off[e] = acc; s_base[e] = acc; acc += s_cnt[e]; }
        g_off[dE] = acc;
    }
    __syncthreads();
    if (t < dE) s_cnt[t] = 0;
    __syncthreads();
    for (int p = t; p < dNK; p += blockDim.x) {
        int e = idx[p];
        int slot = s_base[e] + atomicAdd(&s_cnt[e], 1);
        g_pairs[slot] = p;
    }
}

// ============ GEMM1: h = silu(x@w1) * (x@w3), CTA 128x128, warp 64x32 ============
__global__ void __launch_bounds__(NTH)
gemm1_mma(const float* __restrict__ x,
          const float* __restrict__ w1,
          const float* __restrict__ w3) {
    const int e    = blockIdx.z;
    const int mEnd = g_off[e + 1];
    const int m0   = g_off[e] + blockIdx.y * TM;
    if (m0 >= mEnd) return;
    const int i0 = blockIdx.x * TN;

    extern __shared__ uint32_t dsm[];
    __shared__ int s_tok[TM];

    const int t = threadIdx.x;
    const int w = t >> 5, l = t & 31;
    const int wm = w & 1, wn = w >> 1;       // 2 x 4 warps, warp tile 64x32
    const int lr = l >> 2, lc = l & 3;

    if (t < TM) { int s = m0 + t; s_tok[t] = (s < mEnd) ? g_pairs[s] / dK : -1; }
    __syncthreads();

    const float* w1e = w1 + (size_t)e * dH * dI + i0;
    const float* w3e = w3 + (size_t)e * dH * dI + i0;

    // per-thread staging coords
    const int aR0 = t >> 2,          aKq0 = t & 3;          // + j*256 -> row += 64
    const int bK0 = t >> 5,          bNq0 = t & 31;         // + j*256 -> k += 8

    float4 rA[2], rB1[2], rB3[2];

    auto ldg_stage = [&](int kt) {
        const int k0 = kt * TBK;
        #pragma unroll
        for (int j = 0; j < 2; ++j) {
            int r = aR0 + j * 64;
            int tok = s_tok[r];
            rA[j] = *(const float4*)(x + (size_t)(tok < 0 ? 0 : tok) * dH + k0 + aKq0 * 4);
        }
        #pragma unroll
        for (int j = 0; j < 2; ++j) {
            int kr = bK0 + j * 8;
            rB1[j] = *(const float4*)(w1e + (size_t)(k0 + kr) * dI + bNq0 * 4);
            rB3[j] = *(const float4*)(w3e + (size_t)(k0 + kr) * dI + bNq0 * 4);
        }
    };
    auto sts_stage = [&](int s) {
        #pragma unroll
        for (int j = 0; j < 2; ++j)
            *(uint4*)&dsm[SA(s, aR0 + j * 64, aKq0 * 4)] = cvt4(rA[j]);
        #pragma unroll
        for (int j = 0; j < 2; ++j) {
            *(uint4*)&dsm[SB1_(s, bK0 + j * 8, bNq0 * 4)] = cvt4(rB1[j]);
            *(uint4*)&dsm[SB3_(s, bK0 + j * 8, bNq0 * 4)] = cvt4(rB3[j]);
        }
    };

    float accG[4][4][4] = {};
    float accU[4][4][4] = {};

    const int KT = dH / TBK;   // 64
    ldg_stage(0);
    sts_stage(0);
    __syncthreads();

    for (int kt = 0; kt < KT; ++kt) {
        const int s = kt & 1;
        if (kt + 1 < KT) ldg_stage(kt + 1);
        #pragma unroll
        for (int ks = 0; ks < 2; ++ks) {
            const int kk = ks * 8 + lc;
            uint32_t af[4][4];
            #pragma unroll
            for (int mi = 0; mi < 4; ++mi) {
                int r = wm * 64 + mi * 16 + lr;
                int c = ks * 8 + lc;
                af[mi][0] = dsm[SA(s, r, c)];
                af[mi][1] = dsm[SA(s, r + 8, c)];
                af[mi][2] = dsm[SA(s, r, c + 4)];
                af[mi][3] = dsm[SA(s, r + 8, c + 4)];
            }
            uint32_t b1f[4][2], b3f[4][2];
            #pragma unroll
            for (int ni = 0; ni < 4; ++ni) {
                int col = wn * 32 + ni * 8 + lr;
                b1f[ni][0] = dsm[SB1_(s, kk, col)];
                b1f[ni][1] = dsm[SB1_(s, kk + 4, col)];
                b3f[ni][0] = dsm[SB3_(s, kk, col)];
                b3f[ni][1] = dsm[SB3_(s, kk + 4, col)];
            }
            #pragma unroll
            for (int mi = 0; mi < 4; ++mi)
                #pragma unroll
                for (int ni = 0; ni < 4; ++ni) {
                    mma_tf32(accG[mi][ni], af[mi], b1f[ni]);
                    mma_tf32(accU[mi][ni], af[mi], b3f[ni]);
                }
        }
        if (kt + 1 < KT) sts_stage(s ^ 1);
        __syncthreads();
    }

    #pragma unroll
    for (int mi = 0; mi < 4; ++mi) {
        int r0 = m0 + wm * 64 + mi * 16 + lr;
        int r1 = r0 + 8;
        #pragma unroll
        for (int ni = 0; ni < 4; ++ni) {
            int c = i0 + wn * 32 + ni * 8 + lc * 2;
            if (r0 < mEnd) {
                float g0 = accG[mi][ni][0], g1 = accG[mi][ni][1];
                float u0 = accU[mi][ni][0], u1 = accU[mi][ni][1];
                float2 h;
                h.x = g0 / (1.0f + __expf(-g0)) * u0;
                h.y = g1 / (1.0f + __expf(-g1)) * u1;
                *(float2*)&g_h[(size_t)r0 * dI + c] = h;
            }
            if (r1 < mEnd) {
                float g2 = accG[mi][ni][2], g3 = accG[mi][ni][3];
                float u2 = accU[mi][ni][2], u3 = accU[mi][ni][3];
                float2 h;
                h.x = g2 / (1.0f + __expf(-g2)) * u2;
                h.y = g3 / (1.0f + __expf(-g3)) * u3;
                *(float2*)&g_h[(size_t)r1 * dI + c] = h;
            }
        }
    }
}

// ============ GEMM2: y = ew * (h @ w2), CTA 128x128, warp 64x32 ============
__global__ void __launch_bounds__(NTH)
gemm2_mma(const float* __restrict__ ew,
          const float* __restrict__ w2) {
    const int e    = blockIdx.z;
    const int mEnd = g_off[e + 1];
    const int m0   = g_off[e] + blockIdx.y * TM;
    if (m0 >= mEnd) return;
    const int h0 = blockIdx.x * TN;

    extern __shared__ uint32_t dsm[];

    const int t = threadIdx.x;
    const int w = t >> 5, l = t & 31;
    const int wm = w & 1, wn = w >> 1;
    const int lr = l >> 2, lc = l & 3;

    const float* w2e = w2 + (size_t)e * dI * dH + h0;

    const int aR0 = t >> 2, aKq0 = t & 3;
    const int bK0 = t >> 5, bNq0 = t & 31;

    float4 rA[2], rB[2];

    auto ldg_stage = [&](int kt) {
        const int k0 = kt * TBK;
        #pragma unroll
        for (int j = 0; j < 2; ++j) {
            int r = aR0 + j * 64;
            int row = (m0 + r < mEnd) ? (m0 + r) : m0;
            rA[j] = *(const float4*)(g_h + (size_t)row * dI + k0 + aKq0 * 4);
        }
        #pragma unroll
        for (int j = 0; j < 2; ++j) {
            int kr = bK0 + j * 8;
            rB[j] = *(const float4*)(w2e + (size_t)(k0 + kr) * dH + bNq0 * 4);
        }
    };
    auto sts_stage = [&](int s) {
        #pragma unroll
        for (int j = 0; j < 2; ++j)
            *(uint4*)&dsm[SA(s, aR0 + j * 64, aKq0 * 4)] = cvt4(rA[j]);
        #pragma unroll
        for (int j = 0; j < 2; ++j)
            *(uint4*)&dsm[SB1_(s, bK0 + j * 8, bNq0 * 4)] = cvt4(rB[j]);
    };

    float acc[4][4][4] = {};

    const int KT = dI / TBK;   // 256
    ldg_stage(0);
    sts_stage(0);
    __syncthreads();

    for (int kt = 0; kt < KT; ++kt) {
        const int s = kt & 1;
        if (kt + 1 < KT) ldg_stage(kt + 1);
        #pragma unroll
        for (int ks = 0; ks < 2; ++ks) {
            const int kk = ks * 8 + lc;
            uint32_t af[4][4];
            #pragma unroll
            for (int mi = 0; mi < 4; ++mi) {
                int r = wm * 64 + mi * 16 + lr;
                int c = ks * 8 + lc;
                af[mi][0] = dsm[SA(s, r, c)];
                af[mi][1] = dsm[SA(s, r + 8, c)];
                af[mi][2] = dsm[SA(s, r, c + 4)];
                af[mi][3] = dsm[SA(s, r + 8, c + 4)];
            }
            uint32_t bf[4][2];
            #pragma unroll
            for (int ni = 0; ni < 4; ++ni) {
                int col = wn * 32 + ni * 8 + lr;
                bf[ni][0] = dsm[SB1_(s, kk, col)];
                bf[ni][1] = dsm[SB1_(s, kk + 4, col)];
            }
            #pragma unroll
            for (int mi = 0; mi < 4; ++mi)
                #pragma unroll
                for (int ni = 0; ni < 4; ++ni)
                    mma_tf32(acc[mi][ni], af[mi], bf[ni]);
        }
        if (kt + 1 < KT) sts_stage(s ^ 1);
        __syncthreads();
    }

    #pragma unroll
    for (int mi = 0; mi < 4; ++mi) {
        int r0 = m0 + wm * 64 + mi * 16 + lr;
        int r1 = r0 + 8;
        int p0 = -1, p1 = -1;
        float wg0 = 0.0f, wg1 = 0.0f;
        if (r0 < mEnd) { p0 = g_pairs[r0]; wg0 = ew[p0]; }
        if (r1 < mEnd) { p1 = g_pairs[r1]; wg1 = ew[p1]; }
        #pragma unroll
        for (int ni = 0; ni < 4; ++ni) {
            int c = h0 + wn * 32 + ni * 8 + lc * 2;
            if (p0 >= 0) {
                float2 v = { wg0 * acc[mi][ni][0], wg0 * acc[mi][ni][1] };
                *(float2*)&g_y[(size_t)p0 * dH + c] = v;
            }
            if (p1 >= 0) {
                float2 v = { wg1 * acc[mi][ni][2], wg1 * acc[mi][ni][3] };
                *(float2*)&g_y[(size_t)p1 * dH + c] = v;
            }
        }
    }
}

// ---- final reduce over top-k: out[n] = y[2n] + y[2n+1] ----
__global__ void reduce_kernel(float* __restrict__ out) {
    int i = blockIdx.x * blockDim.x + threadIdx.x;
    if (i >= dN * dH / 4) return;
    int n  = i / (dH / 4);
    int hg = i % (dH / 4);
    const float4* y0 = (const float4*)&g_y[(size_t)(2 * n) * dH];
    const float4* y1 = (const float4*)&g_y[(size_t)(2 * n + 1) * dH];
    float4 a = y0[hg], b = y1[hg];
    float4 r = { a.x + b.x, a.y + b.y, a.z + b.z, a.w + b.w };
    ((float4*)out)[i] = r;
}

extern "C" void kernel_launch(void* const* d_in, const int* in_sizes, int n_in,
                              void* d_out, int out_size) {
    const float* x   = (const float*)d_in[0];
    const int*   idx = (const int*)  d_in[1];
    const float* ew  = (const float*)d_in[2];
    const float* w1  = (const float*)d_in[3];
    const float* w2  = (const float*)d_in[4];
    const float* w3  = (const float*)d_in[5];
    float* out = (float*)d_out;

    const int smem1 = SMEM1_WORDS * 4;   // ~53 KB
    const int smem2 = SMEM2_WORDS * 4;   // ~37 KB
    cudaFuncSetAttribute(gemm1_mma, cudaFuncAttributeMaxDynamicSharedMemorySize, smem1);
    cudaFuncSetAttribute(gemm2_mma, cudaFuncAttributeMaxDynamicSharedMemorySize, smem2);

    route_kernel<<<1, 256>>>(idx);
    dim3 g1(dI / TN, dNK / TM, dE);   // 32 x 32 x 8 (empty M-tiles early-exit)
    gemm1_mma<<<g1, NTH, smem1>>>(x, w1, w3);
    dim3 g2(dH / TN, dNK / TM, dE);   // 8 x 32 x 8
    gemm2_mma<<<g2, NTH, smem2>>>(ew, w2);
    reduce_kernel<<<(dN * dH / 4 + 255) / 256, 256>>>(out);
}

// round 5
// speedup vs baseline: 1.1382x; 1.1382x over previous
#include <cuda_runtime.h>
#include <cuda_fp16.h>
#include <cstdint>

#define dE 8
#define dH 1024
#define dI 4096
#define dN 2048
#define dK 2
#define dNK 4096

#define TBM 128
#define TBN 64
#define TBK 16
#define NTH 256

// smem half2-word layout: row stride 9 words (8 + 1 pad, odd => conflict-free)
#define AST 9
#define A_WORDS (128 * AST)           // 1152 per stage
#define B_WORDS (64 * AST)            // 576 per stage
#define SA(s, r, c)  ((s) * A_WORDS + (r) * AST + (c))
#define SB1(s, n, c) (2 * A_WORDS + (s) * B_WORDS + (n) * AST + (c))
#define SB3(s, n, c) (2 * A_WORDS + 2 * B_WORDS + (s) * B_WORDS + (n) * AST + (c))

// ---- scratch (device globals; no runtime allocation) ----
__device__ int    g_pairs[dNK];
__device__ int    g_off[dE + 1];
__device__ __half g_h[(size_t)dNK * dI];   // SwiGLU hidden, fp16 (32 MB)
__device__ float  g_y[(size_t)dNK * dH];   // per-pair weighted output (16 MB)

__device__ __forceinline__ uint32_t packh2(float lo, float hi) {
    __half2 h = __floats2half2_rn(lo, hi);   // .x = lo (low 16 bits)
    return *(uint32_t*)&h;
}
__device__ __forceinline__ void mma_f16(float* d, const uint32_t* a, const uint32_t* b) {
    asm volatile("mma.sync.aligned.m16n8k16.row.col.f32.f16.f16.f32 "
                 "{%0,%1,%2,%3}, {%4,%5,%6,%7}, {%8,%9}, {%0,%1,%2,%3};\n"
                 : "+f"(d[0]), "+f"(d[1]), "+f"(d[2]), "+f"(d[3])
                 : "r"(a[0]), "r"(a[1]), "r"(a[2]), "r"(a[3]),
                   "r"(b[0]), "r"(b[1]));
}

// ---- routing: histogram + scan + scatter, single CTA ----
__global__ void route_kernel(const int* __restrict__ idx) {
    __shared__ int s_cnt[dE], s_base[dE];
    int t = threadIdx.x;
    if (t < dE) s_cnt[t] = 0;
    __syncthreads();
    for (int p = t; p < dNK; p += blockDim.x) atomicAdd(&s_cnt[idx[p]], 1);
    __syncthreads();
    if (t == 0) {
        int acc = 0;
        for (int e = 0; e < dE; ++e) { g_off[e] = acc; s_base[e] = acc; acc += s_cnt[e]; }
        g_off[dE] = acc;
    }
    __syncthreads();
    if (t < dE) s_cnt[t] = 0;
    __syncthreads();
    for (int p = t; p < dNK; p += blockDim.x) {
        int e = idx[p];
        int slot = s_base[e] + atomicAdd(&s_cnt[e], 1);
        g_pairs[slot] = p;
    }
}

// ============ GEMM1 (fp16 mma): h = silu(x@w1) * (x@w3) ============
// CTA 128x64, 8 warps (4m x 2n), warp tile 32x32
__global__ void __launch_bounds__(NTH, 2)
gemm1_mma(const float* __restrict__ x,
          const float* __restrict__ w1,
          const float* __restrict__ w3) {
    const int e    = blockIdx.z;
    const int mEnd = g_off[e + 1];
    const int m0   = g_off[e] + blockIdx.y * TBM;
    if (m0 >= mEnd) return;
    const int i0 = blockIdx.x * TBN;

    __shared__ uint32_t dsm[2 * A_WORDS + 4 * B_WORDS];   // 18 KB
    __shared__ int s_tok[TBM];

    const int t = threadIdx.x;
    const int w = t >> 5, l = t & 31;
    const int wm = w & 3, wn = w >> 2;
    const int lr = l >> 2, lc = l & 3;

    if (t < TBM) { int s = m0 + t; s_tok[t] = (s < mEnd) ? g_pairs[s] / dK : -1; }
    __syncthreads();

    const float* w1e = w1 + (size_t)e * dH * dI + i0;
    const float* w3e = w3 + (size_t)e * dH * dI + i0;

    // staging coords
    const int aR = t >> 2, aK = (t & 3) * 4;       // A: rows aR, aR+64; 4 k's
    const int bK = (t >> 5) * 2, bN0 = t & 31;     // B: k pair, n = bN0 + 32j

    float4 rA[2];
    float  rB1[2][2], rB3[2][2];

    auto ldg_stage = [&](int kt) {
        const int k0 = kt * TBK;
        #pragma unroll
        for (int j = 0; j < 2; ++j) {
            int tok = s_tok[aR + j * 64];
            rA[j] = *(const float4*)(x + (size_t)(tok < 0 ? 0 : tok) * dH + k0 + aK);
        }
        #pragma unroll
        for (int j = 0; j < 2; ++j) {
            int n = bN0 + 32 * j;
            const float* p1 = w1e + (size_t)(k0 + bK) * dI + n;
            const float* p3 = w3e + (size_t)(k0 + bK) * dI + n;
            rB1[j][0] = p1[0];  rB1[j][1] = p1[dI];
            rB3[j][0] = p3[0];  rB3[j][1] = p3[dI];
        }
    };
    auto sts_stage = [&](int s) {
        #pragma unroll
        for (int j = 0; j < 2; ++j) {
            uint32_t w0 = packh2(rA[j].x, rA[j].y);
            uint32_t w1_ = packh2(rA[j].z, rA[j].w);
            uint32_t* p = &dsm[SA(s, aR + j * 64, aK >> 1)];
            p[0] = w0; p[1] = w1_;
        }
        #pragma unroll
        for (int j = 0; j < 2; ++j) {
            int n = bN0 + 32 * j;
            dsm[SB1(s, n, bK >> 1)] = packh2(rB1[j][0], rB1[j][1]);
            dsm[SB3(s, n, bK >> 1)] = packh2(rB3[j][0], rB3[j][1]);
        }
    };

    float accG[2][4][4] = {};
    float accU[2][4][4] = {};

    const int KT = dH / TBK;   // 64
    ldg_stage(0);
    sts_stage(0);
    __syncthreads();

    for (int kt = 0; kt < KT; ++kt) {
        const int s = kt & 1;
        if (kt + 1 < KT) ldg_stage(kt + 1);

        uint32_t af[2][4];
        #pragma unroll
        for (int mi = 0; mi < 2; ++mi) {
            int r = wm * 32 + mi * 16 + lr;
            af[mi][0] = dsm[SA(s, r,     lc)];
            af[mi][1] = dsm[SA(s, r + 8, lc)];
            af[mi][2] = dsm[SA(s, r,     lc + 4)];
            af[mi][3] = dsm[SA(s, r + 8, lc + 4)];
        }
        #pragma unroll
        for (int ni = 0; ni < 4; ++ni) {
            int col = wn * 32 + ni * 8 + lr;
            uint32_t b1f[2], b3f[2];
            b1f[0] = dsm[SB1(s, col, lc)];
            b1f[1] = dsm[SB1(s, col, lc + 4)];
            b3f[0] = dsm[SB3(s, col, lc)];
            b3f[1] = dsm[SB3(s, col, lc + 4)];
            #pragma unroll
            for (int mi = 0; mi < 2; ++mi) {
                mma_f16(accG[mi][ni], af[mi], b1f);
                mma_f16(accU[mi][ni], af[mi], b3f);
            }
        }

        if (kt + 1 < KT) sts_stage(s ^ 1);
        __syncthreads();
    }

    #pragma unroll
    for (int mi = 0; mi < 2; ++mi) {
        int r0 = m0 + wm * 32 + mi * 16 + lr;
        int r1 = r0 + 8;
        #pragma unroll
        for (int ni = 0; ni < 4; ++ni) {
            int c = i0 + wn * 32 + ni * 8 + lc * 2;
            if (r0 < mEnd) {
                float g0 = accG[mi][ni][0], g1 = accG[mi][ni][1];
                float u0 = accU[mi][ni][0], u1 = accU[mi][ni][1];
                float h0 = g0 / (1.0f + __expf(-g0)) * u0;
                float h1 = g1 / (1.0f + __expf(-g1)) * u1;
                *(uint32_t*)&g_h[(size_t)r0 * dI + c] = packh2(h0, h1);
            }
            if (r1 < mEnd) {
                float g2 = accG[mi][ni][2], g3 = accG[mi][ni][3];
                float u2 = accU[mi][ni][2], u3 = accU[mi][ni][3];
                float h2 = g2 / (1.0f + __expf(-g2)) * u2;
                float h3 = g3 / (1.0f + __expf(-g3)) * u3;
                *(uint32_t*)&g_h[(size_t)r1 * dI + c] = packh2(h2, h3);
            }
        }
    }
}

// ============ GEMM2 (fp16 mma): y = ew * (h @ w2) ============
__global__ void __launch_bounds__(NTH, 2)
gemm2_mma(const float* __restrict__ ew,
          const float* __restrict__ w2) {
    const int e    = blockIdx.z;
    const int mEnd = g_off[e + 1];
    const int m0   = g_off[e] + blockIdx.y * TBM;
    if (m0 >= mEnd) return;
    const int h0 = blockIdx.x * TBN;

    __shared__ uint32_t dsm[2 * A_WORDS + 2 * B_WORDS];   // 13.5 KB

    const int t = threadIdx.x;
    const int w = t >> 5, l = t & 31;
    const int wm = w & 3, wn = w >> 2;
    const int lr = l >> 2, lc = l & 3;

    const float* w2e = w2 + (size_t)e * dI * dH + h0;

    const int aR = t >> 2, aK = (t & 3) * 4;
    const int bK = (t >> 5) * 2, bN0 = t & 31;

    uint2 rA[2];                       // 4 halfs (4 k's), already packed pairs
    float rB[2][2];

    auto ldg_stage = [&](int kt) {
        const int k0 = kt * TBK;
        #pragma unroll
        for (int j = 0; j < 2; ++j) {
            int r = aR + j * 64;
            int row = (m0 + r < mEnd) ? (m0 + r) : m0;
            rA[j] = *(const uint2*)(g_h + (size_t)row * dI + k0 + aK);
        }
        #pragma unroll
        for (int j = 0; j < 2; ++j) {
            int n = bN0 + 32 * j;
            const float* p = w2e + (size_t)(k0 + bK) * dH + n;
            rB[j][0] = p[0];  rB[j][1] = p[dH];
        }
    };
    auto sts_stage = [&](int s) {
        #pragma unroll
        for (int j = 0; j < 2; ++j) {
            uint32_t* p = &dsm[SA(s, aR + j * 64, aK >> 1)];
            p[0] = rA[j].x; p[1] = rA[j].y;
        }
        #pragma unroll
        for (int j = 0; j < 2; ++j) {
            int n = bN0 + 32 * j;
            dsm[SB1(s, n, bK >> 1)] = packh2(rB[j][0], rB[j][1]);
        }
    };

    float acc[2][4][4] = {};

    const int KT = dI / TBK;   // 256
    ldg_stage(0);
    sts_stage(0);
    __syncthreads();

    for (int kt = 0; kt < KT; ++kt) {
        const int s = kt & 1;
        if (kt + 1 < KT) ldg_stage(kt + 1);

        uint32_t af[2][4];
        #pragma unroll
        for (int mi = 0; mi < 2; ++mi) {
            int r = wm * 32 + mi * 16 + lr;
            af[mi][0] = dsm[SA(s, r,     lc)];
            af[mi][1] = dsm[SA(s, r + 8, lc)];
            af[mi][2] = dsm[SA(s, r,     lc + 4)];
            af[mi][3] = dsm[SA(s, r + 8, lc + 4)];
        }
        #pragma unroll
        for (int ni = 0; ni < 4; ++ni) {
            int col = wn * 32 + ni * 8 + lr;
            uint32_t bf[2];
            bf[0] = dsm[SB1(s, col, lc)];
            bf[1] = dsm[SB1(s, col, lc + 4)];
            #pragma unroll
            for (int mi = 0; mi < 2; ++mi)
                mma_f16(acc[mi][ni], af[mi], bf);
        }

        if (kt + 1 < KT) sts_stage(s ^ 1);
        __syncthreads();
    }

    #pragma unroll
    for (int mi = 0; mi < 2; ++mi) {
        int r0 = m0 + wm * 32 + mi * 16 + lr;
        int r1 = r0 + 8;
        int p0 = -1, p1 = -1;
        float wg0 = 0.0f, wg1 = 0.0f;
        if (r0 < mEnd) { p0 = g_pairs[r0]; wg0 = ew[p0]; }
        if (r1 < mEnd) { p1 = g_pairs[r1]; wg1 = ew[p1]; }
        #pragma unroll
        for (int ni = 0; ni < 4; ++ni) {
            int c = h0 + wn * 32 + ni * 8 + lc * 2;
            if (p0 >= 0) {
                float2 v = { wg0 * acc[mi][ni][0], wg0 * acc[mi][ni][1] };
                *(float2*)&g_y[(size_t)p0 * dH + c] = v;
            }
            if (p1 >= 0) {
                float2 v = { wg1 * acc[mi][ni][2], wg1 * acc[mi][ni][3] };
                *(float2*)&g_y[(size_t)p1 * dH + c] = v;
            }
        }
    }
}

// ---- final reduce over top-k: out[n] = y[2n] + y[2n+1] ----
__global__ void reduce_kernel(float* __restrict__ out) {
    int i = blockIdx.x * blockDim.x + threadIdx.x;
    if (i >= dN * dH / 4) return;
    int n  = i / (dH / 4);
    int hg = i % (dH / 4);
    const float4* y0 = (const float4*)&g_y[(size_t)(2 * n) * dH];
    const float4* y1 = (const float4*)&g_y[(size_t)(2 * n + 1) * dH];
    float4 a = y0[hg], b = y1[hg];
    float4 r = { a.x + b.x, a.y + b.y, a.z + b.z, a.w + b.w };
    ((float4*)out)[i] = r;
}

extern "C" void kernel_launch(void* const* d_in, const int* in_sizes, int n_in,
                              void* d_out, int out_size) {
    const float* x   = (const float*)d_in[0];
    const int*   idx = (const int*)  d_in[1];
    const float* ew  = (const float*)d_in[2];
    const float* w1  = (const float*)d_in[3];
    const float* w2  = (const float*)d_in[4];
    const float* w3  = (const float*)d_in[5];
    float* out = (float*)d_out;

    route_kernel<<<1, 256>>>(idx);
    dim3 g1(dI / TBN, dNK / TBM, dE);   // 64 x 32 x 8 (empty M-tiles early-exit)
    gemm1_mma<<<g1, NTH>>>(x, w1, w3);
    dim3 g2(dH / TBN, dNK / TBM, dE);   // 16 x 32 x 8
    gemm2_mma<<<g2, NTH>>>(ew, w2);
    reduce_kernel<<<(dN * dH / 4 + 255) / 256, 256>>>(out);
}